// round 1
// baseline (speedup 1.0000x reference)
#include <cuda_runtime.h>

#define BB 4
#define CC 256
#define CQ 64
#define NN 4096

// ---------------- scratch (device globals; no allocations) ----------------
__device__ float g_Wqk[128 * CC];                       // Wq (64 rows) stacked on Wk (64 rows)
__device__ float g_QK[(size_t)BB * 128 * NN];           // Q rows 0..63, K rows 64..127 per batch
__device__ float g_V[(size_t)BB * CC * NN];
__device__ float g_A[(size_t)BB * NN * NN];             // energy -> softmaxed attention (268 MB)
__device__ float g_colsum[BB * NN];
__device__ float g_XR[(size_t)BB * CC * NN];
__device__ float g_T[(size_t)BB * CC * NN];
__device__ float g_sum[CC];
__device__ float g_sumsq[CC];
__device__ float g_scale[CC];
__device__ float g_shift[CC];

// ---------------- generic 128x128 register-blocked SGEMM ----------------
// C[row,col] = sum_k A[row,k] * (B1-B2)[k,col]  (+bias[row]) (*colscale[col]) (+BN stats)
// A row-major [M,K], B row-major [K,NN], C row-major [M,NN]
template <bool HAS_BIAS, bool HAS_COLSCALE, bool B_DIFF, bool STATS>
__global__ __launch_bounds__(256)
void gemm_kernel(const float* __restrict__ A, size_t aBS,
                 const float* __restrict__ B1, size_t bBS,
                 const float* __restrict__ B2,
                 const float* __restrict__ bias,
                 const float* __restrict__ colsum,
                 float* __restrict__ C, size_t cBS,
                 int K)
{
    const int bz = blockIdx.z;
    const float* Ab  = A  + (size_t)bz * aBS;
    const float* Bb  = B1 + (size_t)bz * bBS;
    const float* B2b = B_DIFF ? (B2 + (size_t)bz * bBS) : nullptr;
    float* Cb = C + (size_t)bz * cBS;

    const int row0 = blockIdx.y * 128;
    const int col0 = blockIdx.x * 128;

    __shared__ float As[8][132];
    __shared__ float Bs[8][132];

    const int tid = threadIdx.x;
    const int tx = tid & 15, ty = tid >> 4;

    float acc[8][8];
#pragma unroll
    for (int i = 0; i < 8; i++)
#pragma unroll
        for (int j = 0; j < 8; j++) acc[i][j] = 0.f;

    const int a_r = tid >> 1, a_c = (tid & 1) * 4;   // A tile: 128 rows x 8 k
    const int b_k = tid >> 5, b_c = (tid & 31) * 4;  // B tile: 8 k x 128 cols

    const float* aPtr  = Ab + (size_t)(row0 + a_r) * K + a_c;
    const float* bPtr  = Bb + (size_t)b_k * NN + col0 + b_c;
    const float* b2Ptr = B_DIFF ? (B2b + (size_t)b_k * NN + col0 + b_c) : nullptr;

    for (int kb = 0; kb < K; kb += 8) {
        float4 av = *(const float4*)aPtr;  aPtr += 8;
        float4 bv = *(const float4*)bPtr;  bPtr += (size_t)8 * NN;
        if (B_DIFF) {
            float4 b2 = *(const float4*)b2Ptr;  b2Ptr += (size_t)8 * NN;
            bv.x -= b2.x; bv.y -= b2.y; bv.z -= b2.z; bv.w -= b2.w;
        }
        __syncthreads();
        As[a_c + 0][a_r] = av.x;
        As[a_c + 1][a_r] = av.y;
        As[a_c + 2][a_r] = av.z;
        As[a_c + 3][a_r] = av.w;
        *(float4*)&Bs[b_k][b_c] = bv;
        __syncthreads();
#pragma unroll
        for (int kk = 0; kk < 8; kk++) {
            float ra[8], rb[8];
            *(float4*)&ra[0] = *(const float4*)&As[kk][ty * 8];
            *(float4*)&ra[4] = *(const float4*)&As[kk][ty * 8 + 4];
            *(float4*)&rb[0] = *(const float4*)&Bs[kk][tx * 8];
            *(float4*)&rb[4] = *(const float4*)&Bs[kk][tx * 8 + 4];
#pragma unroll
            for (int i = 0; i < 8; i++)
#pragma unroll
                for (int j = 0; j < 8; j++) acc[i][j] += ra[i] * rb[j];
        }
    }

    float cs[8];
    if (HAS_COLSCALE) {
#pragma unroll
        for (int j = 0; j < 8; j++)
            cs[j] = 1.0f / (1e-9f + colsum[(size_t)bz * NN + col0 + tx * 8 + j]);
    }

#pragma unroll
    for (int i = 0; i < 8; i++) {
        const int row = row0 + ty * 8 + i;
        const float bi = HAS_BIAS ? bias[row] : 0.f;
        float vals[8];
        float s = 0.f, s2 = 0.f;
#pragma unroll
        for (int j = 0; j < 8; j++) {
            float v = acc[i][j] + bi;
            if (HAS_COLSCALE) v *= cs[j];
            vals[j] = v;
            if (STATS) { s += v; s2 += v * v; }
        }
        float4* outp = (float4*)&Cb[(size_t)row * NN + col0 + tx * 8];
        outp[0] = *(float4*)&vals[0];
        outp[1] = *(float4*)&vals[4];
        if (STATS) {
            atomicAdd(&g_sum[row], s);
            atomicAdd(&g_sumsq[row], s2);
        }
    }
}

// ---------------- energy: E[n,m] = sum_{o<64} Q[o,n]*K[o,m] ----------------
__global__ __launch_bounds__(256)
void energy_kernel(const float* __restrict__ QK, float* __restrict__ E)
{
    const int bz = blockIdx.z;
    const float* Q  = QK + (size_t)bz * 128 * NN;
    const float* Kp = Q + (size_t)CQ * NN;
    float* Eb = E + (size_t)bz * NN * NN;

    const int row0 = blockIdx.y * 128;
    const int col0 = blockIdx.x * 128;

    __shared__ float As[8][132];
    __shared__ float Bs[8][132];

    const int tid = threadIdx.x;
    const int tx = tid & 15, ty = tid >> 4;

    float acc[8][8];
#pragma unroll
    for (int i = 0; i < 8; i++)
#pragma unroll
        for (int j = 0; j < 8; j++) acc[i][j] = 0.f;

    const int lk = tid >> 5, lc = (tid & 31) * 4;

    for (int kb = 0; kb < CQ; kb += 8) {
        float4 qv = *(const float4*)&Q [(size_t)(kb + lk) * NN + row0 + lc];
        float4 kv = *(const float4*)&Kp[(size_t)(kb + lk) * NN + col0 + lc];
        __syncthreads();
        *(float4*)&As[lk][lc] = qv;
        *(float4*)&Bs[lk][lc] = kv;
        __syncthreads();
#pragma unroll
        for (int kk = 0; kk < 8; kk++) {
            float ra[8], rb[8];
            *(float4*)&ra[0] = *(const float4*)&As[kk][ty * 8];
            *(float4*)&ra[4] = *(const float4*)&As[kk][ty * 8 + 4];
            *(float4*)&rb[0] = *(const float4*)&Bs[kk][tx * 8];
            *(float4*)&rb[4] = *(const float4*)&Bs[kk][tx * 8 + 4];
#pragma unroll
            for (int i = 0; i < 8; i++)
#pragma unroll
                for (int j = 0; j < 8; j++) acc[i][j] += ra[i] * rb[j];
        }
    }
#pragma unroll
    for (int i = 0; i < 8; i++) {
        const int row = row0 + ty * 8 + i;
        float4* outp = (float4*)&Eb[(size_t)row * NN + col0 + tx * 8];
        outp[0] = *(float4*)&acc[i][0];
        outp[1] = *(float4*)&acc[i][4];
    }
}

// ---------------- row softmax in-place ----------------
__global__ void softmax_kernel(float* __restrict__ A)
{
    float* row = A + ((size_t)blockIdx.y * NN + blockIdx.x) * NN;
    const int tid = threadIdx.x;
    __shared__ float red[256];

    float v[16];
    float m = -1e30f;
#pragma unroll
    for (int i = 0; i < 16; i++) {
        v[i] = row[tid + i * 256];
        m = fmaxf(m, v[i]);
    }
    red[tid] = m; __syncthreads();
    for (int s = 128; s > 0; s >>= 1) {
        if (tid < s) red[tid] = fmaxf(red[tid], red[tid + s]);
        __syncthreads();
    }
    m = red[0]; __syncthreads();

    float sum = 0.f;
#pragma unroll
    for (int i = 0; i < 16; i++) {
        v[i] = __expf(v[i] - m);
        sum += v[i];
    }
    red[tid] = sum; __syncthreads();
    for (int s = 128; s > 0; s >>= 1) {
        if (tid < s) red[tid] += red[tid + s];
        __syncthreads();
    }
    const float inv = 1.0f / red[0];
#pragma unroll
    for (int i = 0; i < 16; i++) row[tid + i * 256] = v[i] * inv;
}

// ---------------- column sums of attention (over rows n) ----------------
__global__ void colsum_kernel(const float* __restrict__ A)
{
    const int m = blockIdx.x * 256 + threadIdx.x;
    const int b = blockIdx.z;
    const int n0 = blockIdx.y * 128;
    const float* Ab = A + (size_t)b * NN * NN;
    float s = 0.f;
#pragma unroll 4
    for (int n = 0; n < 128; n++) s += Ab[(size_t)(n0 + n) * NN + m];
    atomicAdd(&g_colsum[b * NN + m], s);
}

// ---------------- misc small kernels ----------------
__global__ void concat_wqk_kernel(const float* __restrict__ Wq, const float* __restrict__ Wk)
{
    const int t = blockIdx.x * 256 + threadIdx.x;  // 16384 each
    g_Wqk[t] = Wq[t];
    g_Wqk[CQ * CC + t] = Wk[t];
}

__global__ void zero_kernel()
{
    const int t = blockIdx.x * 256 + threadIdx.x;
    if (t < CC) { g_sum[t] = 0.f; g_sumsq[t] = 0.f; }
    if (t < BB * NN) g_colsum[t] = 0.f;
}

__global__ void bn_finalize_kernel(const float* __restrict__ gamma, const float* __restrict__ beta)
{
    const int c = threadIdx.x;
    const float cnt = (float)(BB * NN);
    const float mean = g_sum[c] / cnt;
    const float var = g_sumsq[c] / cnt - mean * mean;
    const float sc = gamma[c] * rsqrtf(var + 1e-5f);
    g_scale[c] = sc;
    g_shift[c] = beta[c] - mean * sc;
}

__global__ void final_kernel(const float* __restrict__ x, float* __restrict__ out)
{
    const size_t idx = (size_t)blockIdx.x * 256 + threadIdx.x;
    const int c = (int)((idx >> 12) & (CC - 1));  // N = 4096 = 2^12
    const float t = g_T[idx] * g_scale[c] + g_shift[c];
    out[idx] = x[idx] + fmaxf(t, 0.f);
}

// ---------------- launch ----------------
extern "C" void kernel_launch(void* const* d_in, const int* in_sizes, int n_in,
                              void* d_out, int out_size)
{
    const float* x     = (const float*)d_in[0];
    const float* Wq    = (const float*)d_in[1];
    const float* Wk    = (const float*)d_in[2];
    const float* Wv    = (const float*)d_in[3];
    const float* bv    = (const float*)d_in[4];
    const float* Wt    = (const float*)d_in[5];
    const float* bt    = (const float*)d_in[6];
    const float* gamma = (const float*)d_in[7];
    const float* beta  = (const float*)d_in[8];
    float* out = (float*)d_out;

    float *pWqk, *pQK, *pV, *pA, *pColsum, *pXR, *pT;
    cudaGetSymbolAddress((void**)&pWqk, g_Wqk);
    cudaGetSymbolAddress((void**)&pQK, g_QK);
    cudaGetSymbolAddress((void**)&pV, g_V);
    cudaGetSymbolAddress((void**)&pA, g_A);
    cudaGetSymbolAddress((void**)&pColsum, g_colsum);
    cudaGetSymbolAddress((void**)&pXR, g_XR);
    cudaGetSymbolAddress((void**)&pT, g_T);

    concat_wqk_kernel<<<CQ * CC / 256, 256>>>(Wq, Wk);
    zero_kernel<<<BB * NN / 256, 256>>>();

    // QK projection: [128,256] @ [256,4096] per batch
    gemm_kernel<false, false, false, false><<<dim3(NN / 128, 1, BB), 256>>>(
        pWqk, 0, x, (size_t)CC * NN, nullptr, nullptr, nullptr,
        pQK, (size_t)128 * NN, CC);

    // V projection: [256,256] @ [256,4096] + bv
    gemm_kernel<true, false, false, false><<<dim3(NN / 128, CC / 128, BB), 256>>>(
        Wv, 0, x, (size_t)CC * NN, nullptr, bv, nullptr,
        pV, (size_t)CC * NN, CC);

    // energy -> g_A
    energy_kernel<<<dim3(NN / 128, NN / 128, BB), 256>>>(pQK, pA);

    // row softmax in-place
    softmax_kernel<<<dim3(NN, BB), 256>>>(pA);

    // column sums for L1 renorm
    colsum_kernel<<<dim3(NN / 256, NN / 128, BB), 256>>>(pA);

    // x_r = V @ A, columns scaled by 1/(1e-9 + colsum)
    gemm_kernel<false, true, false, false><<<dim3(NN / 128, CC / 128, BB), 256>>>(
        pV, (size_t)CC * NN, pA, (size_t)NN * NN, nullptr, nullptr, pColsum,
        pXR, (size_t)CC * NN, NN);

    // t = Wt @ (x - x_r) + bt, with BN stats accumulation
    gemm_kernel<true, false, true, true><<<dim3(NN / 128, CC / 128, BB), 256>>>(
        Wt, 0, x, (size_t)CC * NN, pXR, bt, nullptr,
        pT, (size_t)CC * NN, CC);

    bn_finalize_kernel<<<1, CC>>>(gamma, beta);

    final_kernel<<<(size_t)BB * CC * NN / 256, 256>>>(x, out);
}

// round 3
// speedup vs baseline: 1.7070x; 1.7070x over previous
#include <cuda_runtime.h>
#include <cuda_bf16.h>
#include <cstdint>

#define BB 4
#define CC 256
#define CQ 64
#define NN 4096

// ---------------- scratch (device globals; no allocations) ----------------
__device__ float g_Wqk[128 * CC];
__device__ float g_QK[(size_t)BB * 128 * NN];           // Q rows 0..63, K rows 64..127
__device__ float g_V[(size_t)BB * CC * NN];
__device__ float g_E[(size_t)BB * NN * NN];             // energy fp32 (268 MB)
__device__ __nv_bfloat16 g_Ahi[(size_t)BB * NN * NN];   // softmaxed attention hi
__device__ __nv_bfloat16 g_Alo[(size_t)BB * NN * NN];   // lo
__device__ __nv_bfloat16 g_Vhi[(size_t)BB * CC * NN];
__device__ __nv_bfloat16 g_Vlo[(size_t)BB * CC * NN];
__device__ __nv_bfloat16 g_Qthi[(size_t)BB * NN * CQ];  // Q transposed [n][o]
__device__ __nv_bfloat16 g_Qtlo[(size_t)BB * NN * CQ];
__device__ __nv_bfloat16 g_Khi[(size_t)BB * CQ * NN];
__device__ __nv_bfloat16 g_Klo[(size_t)BB * CQ * NN];
__device__ float g_colsum[BB * NN];
__device__ float g_XR[(size_t)BB * CC * NN];
__device__ float g_T[(size_t)BB * CC * NN];
__device__ float g_sum[CC];
__device__ float g_sumsq[CC];
__device__ float g_scale[CC];
__device__ float g_shift[CC];

// ---------------- PTX helpers ----------------
__device__ __forceinline__ void mma16816(float* c, const uint32_t* a, const uint32_t* b) {
    asm volatile(
        "mma.sync.aligned.m16n8k16.row.col.f32.bf16.bf16.f32 "
        "{%0,%1,%2,%3}, {%4,%5,%6,%7}, {%8,%9}, {%0,%1,%2,%3};\n"
        : "+f"(c[0]), "+f"(c[1]), "+f"(c[2]), "+f"(c[3])
        : "r"(a[0]), "r"(a[1]), "r"(a[2]), "r"(a[3]), "r"(b[0]), "r"(b[1]));
}
__device__ __forceinline__ void ldsm4(uint32_t* r, uint32_t addr) {
    asm volatile("ldmatrix.sync.aligned.m8n8.x4.shared.b16 {%0,%1,%2,%3}, [%4];"
        : "=r"(r[0]), "=r"(r[1]), "=r"(r[2]), "=r"(r[3]) : "r"(addr));
}
__device__ __forceinline__ void ldsm4t(uint32_t* r, uint32_t addr) {
    asm volatile("ldmatrix.sync.aligned.m8n8.x4.trans.shared.b16 {%0,%1,%2,%3}, [%4];"
        : "=r"(r[0]), "=r"(r[1]), "=r"(r[2]), "=r"(r[3]) : "r"(addr));
}
__device__ __forceinline__ void cpasync16(uint32_t saddr, const void* g) {
    asm volatile("cp.async.cg.shared.global [%0], [%1], 16;" :: "r"(saddr), "l"(g));
}
__device__ __forceinline__ void cp_commit() { asm volatile("cp.async.commit_group;" ::: "memory"); }

// ---------------- bf16-split tensor-core GEMM ----------------
// C[M,N] += (Ahi+Alo)[M,K] @ (Bhi+Blo)[K,N]  (3-product split; ldb=ldc=NN)
// block tile 128x128, warp tile 32x64, k-tile 16, 2-stage cp.async pipeline
#define SA_STRIDE 24   // halves per A row (padded; 48B, 16B-aligned, conflict-free)
#define SB_STRIDE 136  // halves per B row (272B)

__global__ __launch_bounds__(256)
void mma_gemm_kernel(const __nv_bfloat16* __restrict__ Ahi, const __nv_bfloat16* __restrict__ Alo,
                     int lda, size_t aBS,
                     const __nv_bfloat16* __restrict__ Bhi, const __nv_bfloat16* __restrict__ Blo,
                     size_t bBS,
                     float* __restrict__ C, size_t cBS, int K)
{
    __shared__ __align__(16) __nv_bfloat16 sA[2][2][128 * SA_STRIDE];
    __shared__ __align__(16) __nv_bfloat16 sB[2][2][16 * SB_STRIDE];

    const int bz = blockIdx.z;
    Ahi += (size_t)bz * aBS;  Alo += (size_t)bz * aBS;
    Bhi += (size_t)bz * bBS;  Blo += (size_t)bz * bBS;
    C   += (size_t)bz * cBS;

    const int row0 = blockIdx.y * 128;
    const int col0 = blockIdx.x * 128;
    const int tid  = threadIdx.x;
    const int lane = tid & 31, warp = tid >> 5;
    const int wm = warp & 3;        // 0..3, 32 rows each
    const int wn = warp >> 2;       // 0..1, 64 cols each

    // global load mapping (one 16B vector per thread per matrix per stage)
    const int ar = tid >> 1, ac = (tid & 1) * 8;      // A: 128 rows x 16 k
    const int bk = tid >> 4, bc = (tid & 15) * 8;     // B: 16 k x 128 cols
    const size_t gA = (size_t)(row0 + ar) * lda + ac;
    const size_t gB = (size_t)bk * NN + col0 + bc;

    const uint32_t sAbase = (uint32_t)__cvta_generic_to_shared(&sA[0][0][0]);
    const uint32_t sBbase = (uint32_t)__cvta_generic_to_shared(&sB[0][0][0]);
    const uint32_t sAst = (uint32_t)(ar * SA_STRIDE + ac) * 2;
    const uint32_t sBst = (uint32_t)(bk * SB_STRIDE + bc) * 2;

    float acc[2][8][4];
#pragma unroll
    for (int i = 0; i < 2; i++)
#pragma unroll
        for (int j = 0; j < 8; j++)
#pragma unroll
            for (int k = 0; k < 4; k++) acc[i][j][k] = 0.f;

    const int KT = K >> 4;

    auto issue = [&](int kt, int stage) {
        const size_t ka = gA + (size_t)kt * 16;
        const size_t kb = gB + (size_t)kt * 16 * NN;
        const uint32_t aoff = sAbase + stage * (2 * 128 * SA_STRIDE * 2) + sAst;
        const uint32_t boff = sBbase + stage * (2 * 16 * SB_STRIDE * 2) + sBst;
        cpasync16(aoff,                         Ahi + ka);
        cpasync16(aoff + 128 * SA_STRIDE * 2,   Alo + ka);
        cpasync16(boff,                         Bhi + kb);
        cpasync16(boff + 16 * SB_STRIDE * 2,    Blo + kb);
    };

    issue(0, 0); cp_commit();

    // ldmatrix addresses
    const int lr = lane & 15, lc8 = (lane >> 4) * 8;
    const uint32_t aAddrBase = sAbase + ((wm * 32 + lr) * SA_STRIDE + lc8) * 2;
    const uint32_t bAddrBase = sBbase + (lr * SB_STRIDE + wn * 64 + lc8) * 2;

    for (int kt = 0; kt < KT; kt++) {
        const int cur = kt & 1;
        if (kt + 1 < KT) {
            issue(kt + 1, cur ^ 1); cp_commit();
            asm volatile("cp.async.wait_group 1;" ::: "memory");
        } else {
            asm volatile("cp.async.wait_group 0;" ::: "memory");
        }
        __syncthreads();

        const uint32_t aS = cur * (2u * 128 * SA_STRIDE * 2);
        const uint32_t bS = cur * (2u * 16 * SB_STRIDE * 2);

        uint32_t ah[2][4], al[2][4];
#pragma unroll
        for (int mi = 0; mi < 2; mi++) {
            ldsm4(ah[mi], aAddrBase + aS + mi * 16 * SA_STRIDE * 2);
            ldsm4(al[mi], aAddrBase + aS + (128 * SA_STRIDE + mi * 16 * SA_STRIDE) * 2);
        }
        uint32_t bh[4][4], bl[4][4];
#pragma unroll
        for (int j = 0; j < 4; j++) {
            ldsm4t(bh[j], bAddrBase + bS + j * 16 * 2);
            ldsm4t(bl[j], bAddrBase + bS + 16 * SB_STRIDE * 2 + j * 16 * 2);  // lo plane, FIXED offset
        }
#pragma unroll
        for (int mi = 0; mi < 2; mi++) {
#pragma unroll
            for (int j = 0; j < 4; j++) {
                // hi*hi
                mma16816(acc[mi][2 * j],     ah[mi], &bh[j][0]);
                mma16816(acc[mi][2 * j + 1], ah[mi], &bh[j][2]);
                // hi*lo
                mma16816(acc[mi][2 * j],     ah[mi], &bl[j][0]);
                mma16816(acc[mi][2 * j + 1], ah[mi], &bl[j][2]);
                // lo*hi
                mma16816(acc[mi][2 * j],     al[mi], &bh[j][0]);
                mma16816(acc[mi][2 * j + 1], al[mi], &bh[j][2]);
            }
        }
        __syncthreads();
    }

    // epilogue
    const int gid = lane >> 2, t4 = lane & 3;
#pragma unroll
    for (int mi = 0; mi < 2; mi++) {
#pragma unroll
        for (int nj = 0; nj < 8; nj++) {
            const int row = row0 + wm * 32 + mi * 16 + gid;
            const int col = col0 + wn * 64 + nj * 8 + t4 * 2;
            *(float2*)&C[(size_t)row * NN + col]       = make_float2(acc[mi][nj][0], acc[mi][nj][1]);
            *(float2*)&C[(size_t)(row + 8) * NN + col] = make_float2(acc[mi][nj][2], acc[mi][nj][3]);
        }
    }
}

// ---------------- fp32 128x128 register-blocked SGEMM (proj + transform) ----------------
// C = A @ B1  (or A @ (B1 - B2*colscale)) (+bias) (+BN stats)
template <bool HAS_BIAS, bool B_DIFF, bool STATS>
__global__ __launch_bounds__(256)
void gemm_kernel(const float* __restrict__ A, size_t aBS,
                 const float* __restrict__ B1, size_t bBS,
                 const float* __restrict__ B2,
                 const float* __restrict__ bias,
                 const float* __restrict__ colsum,
                 float* __restrict__ C, size_t cBS,
                 int K)
{
    const int bz = blockIdx.z;
    const float* Ab  = A  + (size_t)bz * aBS;
    const float* Bb  = B1 + (size_t)bz * bBS;
    const float* B2b = B_DIFF ? (B2 + (size_t)bz * bBS) : nullptr;
    float* Cb = C + (size_t)bz * cBS;

    const int row0 = blockIdx.y * 128;
    const int col0 = blockIdx.x * 128;

    __shared__ float As[8][132];
    __shared__ float Bs[8][132];

    const int tid = threadIdx.x;
    const int tx = tid & 15, ty = tid >> 4;

    float acc[8][8];
#pragma unroll
    for (int i = 0; i < 8; i++)
#pragma unroll
        for (int j = 0; j < 8; j++) acc[i][j] = 0.f;

    const int a_r = tid >> 1, a_c = (tid & 1) * 4;
    const int b_k = tid >> 5, b_c = (tid & 31) * 4;

    const float* aPtr  = Ab + (size_t)(row0 + a_r) * K + a_c;
    const float* bPtr  = Bb + (size_t)b_k * NN + col0 + b_c;
    const float* b2Ptr = B_DIFF ? (B2b + (size_t)b_k * NN + col0 + b_c) : nullptr;

    float4 cs4;
    if (B_DIFF) {
        cs4.x = 1.0f / (1e-9f + colsum[(size_t)bz * NN + col0 + b_c + 0]);
        cs4.y = 1.0f / (1e-9f + colsum[(size_t)bz * NN + col0 + b_c + 1]);
        cs4.z = 1.0f / (1e-9f + colsum[(size_t)bz * NN + col0 + b_c + 2]);
        cs4.w = 1.0f / (1e-9f + colsum[(size_t)bz * NN + col0 + b_c + 3]);
    }

    for (int kb = 0; kb < K; kb += 8) {
        float4 av = *(const float4*)aPtr;  aPtr += 8;
        float4 bv = *(const float4*)bPtr;  bPtr += (size_t)8 * NN;
        if (B_DIFF) {
            float4 b2 = *(const float4*)b2Ptr;  b2Ptr += (size_t)8 * NN;
            bv.x -= b2.x * cs4.x; bv.y -= b2.y * cs4.y;
            bv.z -= b2.z * cs4.z; bv.w -= b2.w * cs4.w;
        }
        __syncthreads();
        As[a_c + 0][a_r] = av.x;
        As[a_c + 1][a_r] = av.y;
        As[a_c + 2][a_r] = av.z;
        As[a_c + 3][a_r] = av.w;
        *(float4*)&Bs[b_k][b_c] = bv;
        __syncthreads();
#pragma unroll
        for (int kk = 0; kk < 8; kk++) {
            float ra[8], rb[8];
            *(float4*)&ra[0] = *(const float4*)&As[kk][ty * 8];
            *(float4*)&ra[4] = *(const float4*)&As[kk][ty * 8 + 4];
            *(float4*)&rb[0] = *(const float4*)&Bs[kk][tx * 8];
            *(float4*)&rb[4] = *(const float4*)&Bs[kk][tx * 8 + 4];
#pragma unroll
            for (int i = 0; i < 8; i++)
#pragma unroll
                for (int j = 0; j < 8; j++) acc[i][j] += ra[i] * rb[j];
        }
    }

#pragma unroll
    for (int i = 0; i < 8; i++) {
        const int row = row0 + ty * 8 + i;
        const float bi = HAS_BIAS ? bias[row] : 0.f;
        float vals[8];
        float s = 0.f, s2 = 0.f;
#pragma unroll
        for (int j = 0; j < 8; j++) {
            float v = acc[i][j] + bi;
            vals[j] = v;
            if (STATS) { s += v; s2 += v * v; }
        }
        float4* outp = (float4*)&Cb[(size_t)row * NN + col0 + tx * 8];
        outp[0] = *(float4*)&vals[0];
        outp[1] = *(float4*)&vals[4];
        if (STATS) {
            atomicAdd(&g_sum[row], s);
            atomicAdd(&g_sumsq[row], s2);
        }
    }
}

// ---------------- conversions ----------------
__global__ void split_kernel(const float* __restrict__ src, size_t srcBS,
                             __nv_bfloat16* __restrict__ hi, __nv_bfloat16* __restrict__ lo,
                             size_t dstBS)
{
    const size_t i = (size_t)blockIdx.x * 256 + threadIdx.x;
    const float v = src[(size_t)blockIdx.z * srcBS + i];
    const __nv_bfloat16 h = __float2bfloat16(v);
    const size_t o = (size_t)blockIdx.z * dstBS + i;
    hi[o] = h;
    lo[o] = __float2bfloat16(v - __bfloat162float(h));
}

__global__ void qtrans_kernel()
{
    __shared__ float t[32][33];
    const int bz = blockIdx.z;
    const float* Qb = g_QK + (size_t)bz * 128 * NN;
    const int n0 = blockIdx.x * 32, o0 = blockIdx.y * 32;
    const int tx = threadIdx.x, ty = threadIdx.y;
    t[ty][tx] = Qb[(size_t)(o0 + ty) * NN + n0 + tx];
    __syncthreads();
    const float v = t[tx][ty];  // Q[o0+tx][n0+ty]
    const size_t idx = (size_t)bz * NN * CQ + (size_t)(n0 + ty) * CQ + o0 + tx;
    const __nv_bfloat16 h = __float2bfloat16(v);
    g_Qthi[idx] = h;
    g_Qtlo[idx] = __float2bfloat16(v - __bfloat162float(h));
}

// ---------------- row softmax: E fp32 -> A bf16 hi/lo ----------------
__global__ void softmax_kernel()
{
    const size_t rowoff = ((size_t)blockIdx.y * NN + blockIdx.x) * NN;
    const float* row = g_E + rowoff;
    __nv_bfloat16* oh = g_Ahi + rowoff;
    __nv_bfloat16* ol = g_Alo + rowoff;
    const int tid = threadIdx.x;
    __shared__ float red[256];

    float v[16];
    float m = -1e30f;
#pragma unroll
    for (int i = 0; i < 16; i++) {
        v[i] = row[tid + i * 256];
        m = fmaxf(m, v[i]);
    }
    red[tid] = m; __syncthreads();
    for (int s = 128; s > 0; s >>= 1) {
        if (tid < s) red[tid] = fmaxf(red[tid], red[tid + s]);
        __syncthreads();
    }
    m = red[0]; __syncthreads();

    float sum = 0.f;
#pragma unroll
    for (int i = 0; i < 16; i++) {
        v[i] = __expf(v[i] - m);
        sum += v[i];
    }
    red[tid] = sum; __syncthreads();
    for (int s = 128; s > 0; s >>= 1) {
        if (tid < s) red[tid] += red[tid + s];
        __syncthreads();
    }
    const float inv = 1.0f / red[0];
#pragma unroll
    for (int i = 0; i < 16; i++) {
        const float r = v[i] * inv;
        const __nv_bfloat16 h = __float2bfloat16(r);
        oh[tid + i * 256] = h;
        ol[tid + i * 256] = __float2bfloat16(r - __bfloat162float(h));
    }
}

// ---------------- column sums of attention ----------------
__global__ void colsum_kernel()
{
    const int m2 = blockIdx.x * 256 + threadIdx.x;   // bf162 pair index
    const int b = blockIdx.z;
    const int n0 = blockIdx.y * 128;
    const __nv_bfloat162* H = (const __nv_bfloat162*)(g_Ahi + (size_t)b * NN * NN);
    const __nv_bfloat162* L = (const __nv_bfloat162*)(g_Alo + (size_t)b * NN * NN);
    float s0 = 0.f, s1 = 0.f;
#pragma unroll 4
    for (int n = 0; n < 128; n++) {
        const __nv_bfloat162 h = H[(size_t)(n0 + n) * (NN / 2) + m2];
        const __nv_bfloat162 l = L[(size_t)(n0 + n) * (NN / 2) + m2];
        s0 += __bfloat162float(h.x) + __bfloat162float(l.x);
        s1 += __bfloat162float(h.y) + __bfloat162float(l.y);
    }
    atomicAdd(&g_colsum[b * NN + 2 * m2 + 0], s0);
    atomicAdd(&g_colsum[b * NN + 2 * m2 + 1], s1);
}

// ---------------- misc ----------------
__global__ void concat_wqk_kernel(const float* __restrict__ Wq, const float* __restrict__ Wk)
{
    const int t = blockIdx.x * 256 + threadIdx.x;
    g_Wqk[t] = Wq[t];
    g_Wqk[CQ * CC + t] = Wk[t];
}

__global__ void zero_kernel()
{
    const int t = blockIdx.x * 256 + threadIdx.x;
    if (t < CC) { g_sum[t] = 0.f; g_sumsq[t] = 0.f; }
    if (t < BB * NN) g_colsum[t] = 0.f;
}

__global__ void bn_finalize_kernel(const float* __restrict__ gamma, const float* __restrict__ beta)
{
    const int c = threadIdx.x;
    const float cnt = (float)(BB * NN);
    const float mean = g_sum[c] / cnt;
    const float var = g_sumsq[c] / cnt - mean * mean;
    const float sc = gamma[c] * rsqrtf(var + 1e-5f);
    g_scale[c] = sc;
    g_shift[c] = beta[c] - mean * sc;
}

__global__ void final_kernel(const float* __restrict__ x, float* __restrict__ out)
{
    const size_t idx = (size_t)blockIdx.x * 256 + threadIdx.x;
    const int c = (int)((idx >> 12) & (CC - 1));
    const float t = g_T[idx] * g_scale[c] + g_shift[c];
    out[idx] = x[idx] + fmaxf(t, 0.f);
}

// ---------------- launch ----------------
extern "C" void kernel_launch(void* const* d_in, const int* in_sizes, int n_in,
                              void* d_out, int out_size)
{
    const float* x     = (const float*)d_in[0];
    const float* Wq    = (const float*)d_in[1];
    const float* Wk    = (const float*)d_in[2];
    const float* Wv    = (const float*)d_in[3];
    const float* bv    = (const float*)d_in[4];
    const float* Wt    = (const float*)d_in[5];
    const float* bt    = (const float*)d_in[6];
    const float* gamma = (const float*)d_in[7];
    const float* beta  = (const float*)d_in[8];
    float* out = (float*)d_out;

    float *pWqk, *pQK, *pV, *pE, *pColsum, *pXR, *pT;
    __nv_bfloat16 *pAhi, *pAlo, *pVhi, *pVlo, *pQthi, *pQtlo, *pKhi, *pKlo;
    cudaGetSymbolAddress((void**)&pWqk, g_Wqk);
    cudaGetSymbolAddress((void**)&pQK, g_QK);
    cudaGetSymbolAddress((void**)&pV, g_V);
    cudaGetSymbolAddress((void**)&pE, g_E);
    cudaGetSymbolAddress((void**)&pColsum, g_colsum);
    cudaGetSymbolAddress((void**)&pXR, g_XR);
    cudaGetSymbolAddress((void**)&pT, g_T);
    cudaGetSymbolAddress((void**)&pAhi, g_Ahi);
    cudaGetSymbolAddress((void**)&pAlo, g_Alo);
    cudaGetSymbolAddress((void**)&pVhi, g_Vhi);
    cudaGetSymbolAddress((void**)&pVlo, g_Vlo);
    cudaGetSymbolAddress((void**)&pQthi, g_Qthi);
    cudaGetSymbolAddress((void**)&pQtlo, g_Qtlo);
    cudaGetSymbolAddress((void**)&pKhi, g_Khi);
    cudaGetSymbolAddress((void**)&pKlo, g_Klo);

    concat_wqk_kernel<<<CQ * CC / 256, 256>>>(Wq, Wk);
    zero_kernel<<<BB * NN / 256, 256>>>();

    // QK projection (fp32): [128,256] @ [256,4096] per batch
    gemm_kernel<false, false, false><<<dim3(NN / 128, 1, BB), 256>>>(
        pWqk, 0, x, (size_t)CC * NN, nullptr, nullptr, nullptr,
        pQK, (size_t)128 * NN, CC);

    // V projection (fp32): [256,256] @ [256,4096] + bv
    gemm_kernel<true, false, false><<<dim3(NN / 128, CC / 128, BB), 256>>>(
        Wv, 0, x, (size_t)CC * NN, nullptr, bv, nullptr,
        pV, (size_t)CC * NN, CC);

    // bf16 splits
    split_kernel<<<dim3(CC * NN / 256, 1, BB), 256>>>(pV, (size_t)CC * NN, pVhi, pVlo, (size_t)CC * NN);
    split_kernel<<<dim3(CQ * NN / 256, 1, BB), 256>>>(pQK + (size_t)CQ * NN, (size_t)128 * NN,
                                                      pKhi, pKlo, (size_t)CQ * NN);
    qtrans_kernel<<<dim3(NN / 32, CQ / 32, BB), dim3(32, 32)>>>();

    // energy = Qt @ K   (M=4096, N=4096, K=64), tensor cores
    mma_gemm_kernel<<<dim3(NN / 128, NN / 128, BB), 256>>>(
        pQthi, pQtlo, CQ, (size_t)NN * CQ,
        pKhi, pKlo, (size_t)CQ * NN,
        pE, (size_t)NN * NN, CQ);

    // softmax -> bf16 hi/lo attention
    softmax_kernel<<<dim3(NN, BB), 256>>>();

    // column sums for L1 renorm
    colsum_kernel<<<dim3(NN / 512, NN / 128, BB), 256>>>();

    // x_r = V @ A (unscaled; scale folded into transform), tensor cores
    mma_gemm_kernel<<<dim3(NN / 128, CC / 128, BB), 256>>>(
        pVhi, pVlo, NN, (size_t)CC * NN,
        pAhi, pAlo, (size_t)NN * NN,
        pXR, (size_t)CC * NN, NN);

    // t = Wt @ (x - XR*colscale) + bt, with BN stats
    gemm_kernel<true, true, true><<<dim3(NN / 128, CC / 128, BB), 256>>>(
        Wt, 0, x, (size_t)CC * NN, pXR, bt, pColsum,
        pT, (size_t)CC * NN, CC);

    bn_finalize_kernel<<<1, CC>>>(gamma, beta);

    final_kernel<<<(size_t)BB * CC * NN / 256, 256>>>(x, out);
}

// round 4
// speedup vs baseline: 2.9337x; 1.7186x over previous
#include <cuda_runtime.h>
#include <cuda_bf16.h>
#include <cstdint>

#define BB 4
#define CC 256
#define CQ 64
#define NN 4096

// ---------------- scratch (device globals; no allocations) ----------------
__device__ float g_E[(size_t)BB * NN * NN];             // energy fp32 (268 MB)
__device__ __nv_bfloat16 g_A[(size_t)BB * NN * NN];     // softmaxed attention (single plane)
__device__ __nv_bfloat16 g_xhi[(size_t)BB * CC * NN];
__device__ __nv_bfloat16 g_xlo[(size_t)BB * CC * NN];
__device__ __nv_bfloat16 g_Vhi[(size_t)BB * CC * NN];
__device__ __nv_bfloat16 g_Vlo[(size_t)BB * CC * NN];
__device__ __nv_bfloat16 g_dhi[(size_t)BB * CC * NN];   // d = x - xr*colscale, split
__device__ __nv_bfloat16 g_dlo[(size_t)BB * CC * NN];
__device__ __nv_bfloat16 g_Qthi[(size_t)BB * NN * CQ];  // Q transposed [n][o]
__device__ __nv_bfloat16 g_Qtlo[(size_t)BB * NN * CQ];
__device__ __nv_bfloat16 g_Khi[(size_t)BB * CQ * NN];
__device__ __nv_bfloat16 g_Klo[(size_t)BB * CQ * NN];
__device__ __nv_bfloat16 g_Wqkvhi[384 * CC];            // Wq(64) ; Wk(64) ; Wv(256) rows
__device__ __nv_bfloat16 g_Wqkvlo[384 * CC];
__device__ __nv_bfloat16 g_Wthi[CC * CC];
__device__ __nv_bfloat16 g_Wtlo[CC * CC];
__device__ float g_T[(size_t)BB * CC * NN];
__device__ float g_colsum[BB * NN];
__device__ float g_sum[CC];
__device__ float g_sumsq[CC];
__device__ float g_scale[CC];
__device__ float g_shift[CC];

// ---------------- PTX helpers ----------------
__device__ __forceinline__ void mma16816(float* c, const uint32_t* a, const uint32_t* b) {
    asm volatile(
        "mma.sync.aligned.m16n8k16.row.col.f32.bf16.bf16.f32 "
        "{%0,%1,%2,%3}, {%4,%5,%6,%7}, {%8,%9}, {%0,%1,%2,%3};\n"
        : "+f"(c[0]), "+f"(c[1]), "+f"(c[2]), "+f"(c[3])
        : "r"(a[0]), "r"(a[1]), "r"(a[2]), "r"(a[3]), "r"(b[0]), "r"(b[1]));
}
__device__ __forceinline__ void ldsm4(uint32_t* r, uint32_t addr) {
    asm volatile("ldmatrix.sync.aligned.m8n8.x4.shared.b16 {%0,%1,%2,%3}, [%4];"
        : "=r"(r[0]), "=r"(r[1]), "=r"(r[2]), "=r"(r[3]) : "r"(addr));
}
__device__ __forceinline__ void ldsm4t(uint32_t* r, uint32_t addr) {
    asm volatile("ldmatrix.sync.aligned.m8n8.x4.trans.shared.b16 {%0,%1,%2,%3}, [%4];"
        : "=r"(r[0]), "=r"(r[1]), "=r"(r[2]), "=r"(r[3]) : "r"(addr));
}
__device__ __forceinline__ void cpasync16(uint32_t saddr, const void* g) {
    asm volatile("cp.async.cg.shared.global [%0], [%1], 16;" :: "r"(saddr), "l"(g));
}
__device__ __forceinline__ void cp_commit() { asm volatile("cp.async.commit_group;" ::: "memory"); }

__device__ __forceinline__ void split1(float v, __nv_bfloat16& h, __nv_bfloat16& l) {
    h = __float2bfloat16(v);
    l = __float2bfloat16(v - __bfloat162float(h));
}
// pack two adjacent values into hi2/lo2 bf16x2
__device__ __forceinline__ void split_pack(float a, float b, __nv_bfloat162& hi2, __nv_bfloat162& lo2) {
    __nv_bfloat16 ha, la, hb, lb;
    split1(a, ha, la); split1(b, hb, lb);
    hi2.x = ha; hi2.y = hb;
    lo2.x = la; lo2.y = lb;
}

// ---------------- unified bf16-split tensor-core GEMM ----------------
// C[M,N] = (Ahi+Alo)[M,K] @ (B0(+B1))[K,N]     ldb = ldc = NN
// NB = number of B planes (1 or 2). Products: a0b0 (+a0b1 if NB==2) + a1b0.
// EPI: 0 = plain fp32 store to C
//      1 = QKV projection epilogue: by==0 -> rows 0-63 Qt split (transposed),
//          rows 64-127 K split; by>=1 -> V rows (+bias bv) split
//      2 = transform: +bias, BN stats atomics, fp32 store to C (g_T)
//      3 = xr->d: d = aux(x) - acc * (1/(1e-9+colsum[col])), split store to g_dhi/g_dlo
#define SA_STRIDE 24   // halves per A row (48B, 16B-aligned, conflict-free)
#define SB_STRIDE 136  // halves per B row (272B)

template<int NB, int EPI>
__global__ __launch_bounds__(256)
void mma_gemm_kernel(const __nv_bfloat16* __restrict__ Ahi, const __nv_bfloat16* __restrict__ Alo,
                     int lda, size_t aBS,
                     const __nv_bfloat16* __restrict__ B0, const __nv_bfloat16* __restrict__ B1,
                     size_t bBS,
                     float* __restrict__ C, size_t cBS, int K,
                     const float* __restrict__ bias,
                     const float* __restrict__ aux, size_t auxBS)
{
    __shared__ __align__(16) __nv_bfloat16 sA[2][2][128 * SA_STRIDE];
    __shared__ __align__(16) __nv_bfloat16 sB[2][NB][16 * SB_STRIDE];

    const int bz = blockIdx.z;
    Ahi += (size_t)bz * aBS;  Alo += (size_t)bz * aBS;
    B0  += (size_t)bz * bBS;
    if (NB == 2) B1 += (size_t)bz * bBS;
    C += (size_t)bz * cBS;
    if (EPI == 3) aux += (size_t)bz * auxBS;

    const int row0 = blockIdx.y * 128;
    const int col0 = blockIdx.x * 128;
    const int tid  = threadIdx.x;
    const int lane = tid & 31, warp = tid >> 5;
    const int wm = warp & 3;        // 0..3, 32 rows each
    const int wn = warp >> 2;       // 0..1, 64 cols each

    const int ar = tid >> 1, ac = (tid & 1) * 8;      // A: 128 rows x 16 k
    const int bk = tid >> 4, bc = (tid & 15) * 8;     // B: 16 k x 128 cols
    const size_t gA = (size_t)(row0 + ar) * lda + ac;
    const size_t gB = (size_t)bk * NN + col0 + bc;

    const uint32_t sAbase = (uint32_t)__cvta_generic_to_shared(&sA[0][0][0]);
    const uint32_t sBbase = (uint32_t)__cvta_generic_to_shared(&sB[0][0][0]);
    const uint32_t sAst = (uint32_t)(ar * SA_STRIDE + ac) * 2;
    const uint32_t sBst = (uint32_t)(bk * SB_STRIDE + bc) * 2;

    constexpr uint32_t A_PLANE = 128 * SA_STRIDE * 2;
    constexpr uint32_t B_PLANE = 16 * SB_STRIDE * 2;
    constexpr uint32_t A_STAGE = 2 * A_PLANE;
    constexpr uint32_t B_STAGE = NB * B_PLANE;

    float acc[2][8][4];
#pragma unroll
    for (int i = 0; i < 2; i++)
#pragma unroll
        for (int j = 0; j < 8; j++)
#pragma unroll
            for (int k = 0; k < 4; k++) acc[i][j][k] = 0.f;

    const int KT = K >> 4;

    auto issue = [&](int kt, int stage) {
        const size_t ka = gA + (size_t)kt * 16;
        const size_t kb = gB + (size_t)kt * 16 * NN;
        const uint32_t aoff = sAbase + stage * A_STAGE + sAst;
        const uint32_t boff = sBbase + stage * B_STAGE + sBst;
        cpasync16(aoff,           Ahi + ka);
        cpasync16(aoff + A_PLANE, Alo + ka);
        cpasync16(boff,           B0 + kb);
        if (NB == 2) cpasync16(boff + B_PLANE, B1 + kb);
    };

    issue(0, 0); cp_commit();

    const int lr = lane & 15, lc8 = (lane >> 4) * 8;
    const uint32_t aAddrBase = sAbase + ((wm * 32 + lr) * SA_STRIDE + lc8) * 2;
    const uint32_t bAddrBase = sBbase + (lr * SB_STRIDE + wn * 64 + lc8) * 2;

    for (int kt = 0; kt < KT; kt++) {
        const int cur = kt & 1;
        if (kt + 1 < KT) {
            issue(kt + 1, cur ^ 1); cp_commit();
            asm volatile("cp.async.wait_group 1;" ::: "memory");
        } else {
            asm volatile("cp.async.wait_group 0;" ::: "memory");
        }
        __syncthreads();

        const uint32_t aS = cur * A_STAGE;
        const uint32_t bS = cur * B_STAGE;

        uint32_t ah[2][4], al[2][4];
#pragma unroll
        for (int mi = 0; mi < 2; mi++) {
            ldsm4(ah[mi], aAddrBase + aS + mi * 16 * SA_STRIDE * 2);
            ldsm4(al[mi], aAddrBase + aS + A_PLANE + mi * 16 * SA_STRIDE * 2);
        }
        uint32_t bh[4][4], bl[4][4];
#pragma unroll
        for (int j = 0; j < 4; j++) {
            ldsm4t(bh[j], bAddrBase + bS + j * 16 * 2);
            if (NB == 2) ldsm4t(bl[j], bAddrBase + bS + B_PLANE + j * 16 * 2);
        }
#pragma unroll
        for (int mi = 0; mi < 2; mi++) {
#pragma unroll
            for (int j = 0; j < 4; j++) {
                mma16816(acc[mi][2 * j],     ah[mi], &bh[j][0]);
                mma16816(acc[mi][2 * j + 1], ah[mi], &bh[j][2]);
                if (NB == 2) {
                    mma16816(acc[mi][2 * j],     ah[mi], &bl[j][0]);
                    mma16816(acc[mi][2 * j + 1], ah[mi], &bl[j][2]);
                }
                mma16816(acc[mi][2 * j],     al[mi], &bh[j][0]);
                mma16816(acc[mi][2 * j + 1], al[mi], &bh[j][2]);
            }
        }
        __syncthreads();
    }

    // ---------------- epilogues ----------------
    const int gid = lane >> 2, t4 = lane & 3;

    if (EPI == 0) {
#pragma unroll
        for (int mi = 0; mi < 2; mi++)
#pragma unroll
            for (int nj = 0; nj < 8; nj++) {
                const int r = row0 + wm * 32 + mi * 16 + gid;
                const int col = col0 + wn * 64 + nj * 8 + t4 * 2;
                *(float2*)&C[(size_t)r * NN + col]       = make_float2(acc[mi][nj][0], acc[mi][nj][1]);
                *(float2*)&C[(size_t)(r + 8) * NN + col] = make_float2(acc[mi][nj][2], acc[mi][nj][3]);
            }
    }

    if (EPI == 1) {
        const int by = blockIdx.y;
#pragma unroll
        for (int mi = 0; mi < 2; mi++)
#pragma unroll
            for (int nj = 0; nj < 8; nj++) {
                const int r = row0 + wm * 32 + mi * 16 + gid;
                const int col = col0 + wn * 64 + nj * 8 + t4 * 2;
                const float v00 = acc[mi][nj][0], v01 = acc[mi][nj][1];
                const float v10 = acc[mi][nj][2], v11 = acc[mi][nj][3];
                if (by == 0) {
                    if (r < 64) {  // Q -> transposed split [n][o]
                        const size_t base = (size_t)bz * NN * CQ;
                        __nv_bfloat16 h, l;
                        split1(v00, h, l); g_Qthi[base + (size_t)col * CQ + r] = h;       g_Qtlo[base + (size_t)col * CQ + r] = l;
                        split1(v01, h, l); g_Qthi[base + (size_t)(col + 1) * CQ + r] = h; g_Qtlo[base + (size_t)(col + 1) * CQ + r] = l;
                        split1(v10, h, l); g_Qthi[base + (size_t)col * CQ + r + 8] = h;       g_Qtlo[base + (size_t)col * CQ + r + 8] = l;
                        split1(v11, h, l); g_Qthi[base + (size_t)(col + 1) * CQ + r + 8] = h; g_Qtlo[base + (size_t)(col + 1) * CQ + r + 8] = l;
                    } else {       // K -> split [o][n]
                        const int kr = r - 64;
                        const size_t base = (size_t)bz * CQ * NN;
                        __nv_bfloat162 h2, l2;
                        split_pack(v00, v01, h2, l2);
                        *(__nv_bfloat162*)&g_Khi[base + (size_t)kr * NN + col] = h2;
                        *(__nv_bfloat162*)&g_Klo[base + (size_t)kr * NN + col] = l2;
                        split_pack(v10, v11, h2, l2);
                        *(__nv_bfloat162*)&g_Khi[base + (size_t)(kr + 8) * NN + col] = h2;
                        *(__nv_bfloat162*)&g_Klo[base + (size_t)(kr + 8) * NN + col] = l2;
                    }
                } else {           // V rows (+bias)
                    const int vr = r - 128;
                    const size_t base = (size_t)bz * CC * NN;
                    const float b0 = bias[vr], b1 = bias[vr + 8];
                    __nv_bfloat162 h2, l2;
                    split_pack(v00 + b0, v01 + b0, h2, l2);
                    *(__nv_bfloat162*)&g_Vhi[base + (size_t)vr * NN + col] = h2;
                    *(__nv_bfloat162*)&g_Vlo[base + (size_t)vr * NN + col] = l2;
                    split_pack(v10 + b1, v11 + b1, h2, l2);
                    *(__nv_bfloat162*)&g_Vhi[base + (size_t)(vr + 8) * NN + col] = h2;
                    *(__nv_bfloat162*)&g_Vlo[base + (size_t)(vr + 8) * NN + col] = l2;
                }
            }
    }

    if (EPI == 2) {
        float ssum[2][2] = {{0.f, 0.f}, {0.f, 0.f}};
        float ssq[2][2]  = {{0.f, 0.f}, {0.f, 0.f}};
#pragma unroll
        for (int mi = 0; mi < 2; mi++)
#pragma unroll
            for (int nj = 0; nj < 8; nj++) {
                const int r = row0 + wm * 32 + mi * 16 + gid;
                const int col = col0 + wn * 64 + nj * 8 + t4 * 2;
                const float b0 = bias[r], b1 = bias[r + 8];
                const float v00 = acc[mi][nj][0] + b0, v01 = acc[mi][nj][1] + b0;
                const float v10 = acc[mi][nj][2] + b1, v11 = acc[mi][nj][3] + b1;
                *(float2*)&C[(size_t)r * NN + col]       = make_float2(v00, v01);
                *(float2*)&C[(size_t)(r + 8) * NN + col] = make_float2(v10, v11);
                ssum[mi][0] += v00 + v01;  ssq[mi][0] += v00 * v00 + v01 * v01;
                ssum[mi][1] += v10 + v11;  ssq[mi][1] += v10 * v10 + v11 * v11;
            }
#pragma unroll
        for (int mi = 0; mi < 2; mi++)
#pragma unroll
            for (int h = 0; h < 2; h++) {
                const int r = row0 + wm * 32 + mi * 16 + gid + h * 8;
                atomicAdd(&g_sum[r], ssum[mi][h]);
                atomicAdd(&g_sumsq[r], ssq[mi][h]);
            }
    }

    if (EPI == 3) {
#pragma unroll
        for (int mi = 0; mi < 2; mi++)
#pragma unroll
            for (int nj = 0; nj < 8; nj++) {
                const int r = row0 + wm * 32 + mi * 16 + gid;
                const int col = col0 + wn * 64 + nj * 8 + t4 * 2;
                const float cs0 = 1.0f / (1e-9f + g_colsum[bz * NN + col]);
                const float cs1 = 1.0f / (1e-9f + g_colsum[bz * NN + col + 1]);
                const size_t base = (size_t)bz * CC * NN;
                const float d00 = aux[(size_t)r * NN + col]       - acc[mi][nj][0] * cs0;
                const float d01 = aux[(size_t)r * NN + col + 1]   - acc[mi][nj][1] * cs1;
                const float d10 = aux[(size_t)(r + 8) * NN + col]     - acc[mi][nj][2] * cs0;
                const float d11 = aux[(size_t)(r + 8) * NN + col + 1] - acc[mi][nj][3] * cs1;
                __nv_bfloat162 h2, l2;
                split_pack(d00, d01, h2, l2);
                *(__nv_bfloat162*)&g_dhi[base + (size_t)r * NN + col] = h2;
                *(__nv_bfloat162*)&g_dlo[base + (size_t)r * NN + col] = l2;
                split_pack(d10, d11, h2, l2);
                *(__nv_bfloat162*)&g_dhi[base + (size_t)(r + 8) * NN + col] = h2;
                *(__nv_bfloat162*)&g_dlo[base + (size_t)(r + 8) * NN + col] = l2;
            }
    }
}

// ---------------- splits ----------------
__global__ void split_kernel(const float* __restrict__ src, size_t srcBS,
                             __nv_bfloat16* __restrict__ hi, __nv_bfloat16* __restrict__ lo,
                             size_t dstBS)
{
    const size_t i = (size_t)blockIdx.x * 256 + threadIdx.x;
    const float v = src[(size_t)blockIdx.z * srcBS + i];
    __nv_bfloat16 h, l;
    split1(v, h, l);
    const size_t o = (size_t)blockIdx.z * dstBS + i;
    hi[o] = h; lo[o] = l;
}

__global__ void wqkv_split_kernel(const float* __restrict__ Wq, const float* __restrict__ Wk,
                                  const float* __restrict__ Wv)
{
    const int t = blockIdx.x * 256 + threadIdx.x;   // 0..98303
    float v;
    if (t < 64 * CC) v = Wq[t];
    else if (t < 128 * CC) v = Wk[t - 64 * CC];
    else v = Wv[t - 128 * CC];
    __nv_bfloat16 h, l;
    split1(v, h, l);
    g_Wqkvhi[t] = h; g_Wqkvlo[t] = l;
}

// ---------------- row softmax: E fp32 -> A bf16 (single plane) ----------------
__global__ void softmax_kernel()
{
    const size_t rowoff = ((size_t)blockIdx.y * NN + blockIdx.x) * NN;
    const float* row = g_E + rowoff;
    __nv_bfloat16* oa = g_A + rowoff;
    const int tid = threadIdx.x;
    __shared__ float red[256];

    float v[16];
    float m = -1e30f;
#pragma unroll
    for (int i = 0; i < 16; i++) {
        v[i] = row[tid + i * 256];
        m = fmaxf(m, v[i]);
    }
    red[tid] = m; __syncthreads();
    for (int s = 128; s > 0; s >>= 1) {
        if (tid < s) red[tid] = fmaxf(red[tid], red[tid + s]);
        __syncthreads();
    }
    m = red[0]; __syncthreads();

    float sum = 0.f;
#pragma unroll
    for (int i = 0; i < 16; i++) {
        v[i] = __expf(v[i] - m);
        sum += v[i];
    }
    red[tid] = sum; __syncthreads();
    for (int s = 128; s > 0; s >>= 1) {
        if (tid < s) red[tid] += red[tid + s];
        __syncthreads();
    }
    const float inv = 1.0f / red[0];
#pragma unroll
    for (int i = 0; i < 16; i++)
        oa[tid + i * 256] = __float2bfloat16(v[i] * inv);
}

// ---------------- column sums of attention (over query axis n) ----------------
__global__ void colsum_kernel()
{
    const int m2 = blockIdx.x * 256 + threadIdx.x;   // bf162 pair index
    const int b = blockIdx.z;
    const int n0 = blockIdx.y * 128;
    const __nv_bfloat162* A2 = (const __nv_bfloat162*)(g_A + (size_t)b * NN * NN);
    float s0 = 0.f, s1 = 0.f;
#pragma unroll 4
    for (int n = 0; n < 128; n++) {
        const __nv_bfloat162 a = A2[(size_t)(n0 + n) * (NN / 2) + m2];
        s0 += __bfloat162float(a.x);
        s1 += __bfloat162float(a.y);
    }
    atomicAdd(&g_colsum[b * NN + 2 * m2 + 0], s0);
    atomicAdd(&g_colsum[b * NN + 2 * m2 + 1], s1);
}

// ---------------- misc ----------------
__global__ void zero_kernel()
{
    const int t = blockIdx.x * 256 + threadIdx.x;
    if (t < CC) { g_sum[t] = 0.f; g_sumsq[t] = 0.f; }
    if (t < BB * NN) g_colsum[t] = 0.f;
}

__global__ void bn_finalize_kernel(const float* __restrict__ gamma, const float* __restrict__ beta)
{
    const int c = threadIdx.x;
    const float cnt = (float)(BB * NN);
    const float mean = g_sum[c] / cnt;
    const float var = g_sumsq[c] / cnt - mean * mean;
    const float sc = gamma[c] * rsqrtf(var + 1e-5f);
    g_scale[c] = sc;
    g_shift[c] = beta[c] - mean * sc;
}

__global__ void final_kernel(const float* __restrict__ x, float* __restrict__ out)
{
    const size_t idx = (size_t)blockIdx.x * 256 + threadIdx.x;
    const int c = (int)((idx >> 12) & (CC - 1));
    const float t = g_T[idx] * g_scale[c] + g_shift[c];
    out[idx] = x[idx] + fmaxf(t, 0.f);
}

// ---------------- launch ----------------
extern "C" void kernel_launch(void* const* d_in, const int* in_sizes, int n_in,
                              void* d_out, int out_size)
{
    const float* x     = (const float*)d_in[0];
    const float* Wq    = (const float*)d_in[1];
    const float* Wk    = (const float*)d_in[2];
    const float* Wv    = (const float*)d_in[3];
    const float* bv    = (const float*)d_in[4];
    const float* Wt    = (const float*)d_in[5];
    const float* bt    = (const float*)d_in[6];
    const float* gamma = (const float*)d_in[7];
    const float* beta  = (const float*)d_in[8];
    float* out = (float*)d_out;

    float *pE, *pT;
    __nv_bfloat16 *pA, *pXhi, *pXlo, *pVhi, *pVlo, *pDhi, *pDlo;
    __nv_bfloat16 *pQthi, *pQtlo, *pKhi, *pKlo, *pWqkvhi, *pWqkvlo, *pWthi, *pWtlo;
    cudaGetSymbolAddress((void**)&pE, g_E);
    cudaGetSymbolAddress((void**)&pT, g_T);
    cudaGetSymbolAddress((void**)&pA, g_A);
    cudaGetSymbolAddress((void**)&pXhi, g_xhi);
    cudaGetSymbolAddress((void**)&pXlo, g_xlo);
    cudaGetSymbolAddress((void**)&pVhi, g_Vhi);
    cudaGetSymbolAddress((void**)&pVlo, g_Vlo);
    cudaGetSymbolAddress((void**)&pDhi, g_dhi);
    cudaGetSymbolAddress((void**)&pDlo, g_dlo);
    cudaGetSymbolAddress((void**)&pQthi, g_Qthi);
    cudaGetSymbolAddress((void**)&pQtlo, g_Qtlo);
    cudaGetSymbolAddress((void**)&pKhi, g_Khi);
    cudaGetSymbolAddress((void**)&pKlo, g_Klo);
    cudaGetSymbolAddress((void**)&pWqkvhi, g_Wqkvhi);
    cudaGetSymbolAddress((void**)&pWqkvlo, g_Wqkvlo);
    cudaGetSymbolAddress((void**)&pWthi, g_Wthi);
    cudaGetSymbolAddress((void**)&pWtlo, g_Wtlo);

    zero_kernel<<<BB * NN / 256, 256>>>();
    wqkv_split_kernel<<<384 * CC / 256, 256>>>(Wq, Wk, Wv);
    split_kernel<<<dim3(CC * CC / 256, 1, 1), 256>>>(Wt, 0, pWthi, pWtlo, 0);
    split_kernel<<<dim3(CC * NN / 256, 1, BB), 256>>>(x, (size_t)CC * NN, pXhi, pXlo, (size_t)CC * NN);

    // stacked QKV projection: [384,256] @ [256,4096]; epilogue writes Qt/K/V splits
    mma_gemm_kernel<2, 1><<<dim3(NN / 128, 3, BB), 256>>>(
        pWqkvhi, pWqkvlo, CC, 0,
        pXhi, pXlo, (size_t)CC * NN,
        pE /*unused*/, 0, CC, bv, nullptr, 0);

    // energy = Qt @ K  (M=4096, N=4096, K=64) -> fp32 E
    mma_gemm_kernel<2, 0><<<dim3(NN / 128, NN / 128, BB), 256>>>(
        pQthi, pQtlo, CQ, (size_t)NN * CQ,
        pKhi, pKlo, (size_t)CQ * NN,
        pE, (size_t)NN * NN, CQ, nullptr, nullptr, 0);

    // softmax -> A (single bf16)
    softmax_kernel<<<dim3(NN, BB), 256>>>();

    // column sums for L1 renorm
    colsum_kernel<<<dim3(NN / 512, NN / 128, BB), 256>>>();

    // x_r = V @ A; epilogue computes d = x - xr*colscale, writes d splits
    mma_gemm_kernel<1, 3><<<dim3(NN / 128, CC / 128, BB), 256>>>(
        pVhi, pVlo, NN, (size_t)CC * NN,
        pA, nullptr, (size_t)NN * NN,
        pE /*unused*/, 0, NN, nullptr, x, (size_t)CC * NN);

    // t = Wt @ d + bt, with BN stats -> g_T
    mma_gemm_kernel<2, 2><<<dim3(NN / 128, CC / 128, BB), 256>>>(
        pWthi, pWtlo, CC, 0,
        pDhi, pDlo, (size_t)CC * NN,
        pT, (size_t)CC * NN, CC, bt, nullptr, 0);

    bn_finalize_kernel<<<1, CC>>>(gamma, beta);

    final_kernel<<<(size_t)BB * CC * NN / 256, 256>>>(x, out);
}

// round 5
// speedup vs baseline: 3.2939x; 1.1228x over previous
#include <cuda_runtime.h>
#include <cuda_bf16.h>
#include <cstdint>

#define BB 4
#define CC 256
#define CQ 64
#define NN 4096

// ---------------- scratch (device globals; no allocations) ----------------
__device__ __nv_bfloat16 g_A[(size_t)BB * NN * NN];     // unnormalized U = exp(E), bf16
__device__ __nv_bfloat16 g_xhi[(size_t)BB * CC * NN];
__device__ __nv_bfloat16 g_xlo[(size_t)BB * CC * NN];
__device__ __nv_bfloat16 g_Vhi[(size_t)BB * CC * NN];
__device__ __nv_bfloat16 g_Vlo[(size_t)BB * CC * NN];
__device__ __nv_bfloat16 g_dhi[(size_t)BB * CC * NN];   // d = x - xr*colscale, split
__device__ __nv_bfloat16 g_dlo[(size_t)BB * CC * NN];
__device__ __nv_bfloat16 g_Qthi[(size_t)BB * NN * CQ];  // Q transposed [n][o]
__device__ __nv_bfloat16 g_Qtlo[(size_t)BB * NN * CQ];
__device__ __nv_bfloat16 g_Khi[(size_t)BB * CQ * NN];
__device__ __nv_bfloat16 g_Klo[(size_t)BB * CQ * NN];
__device__ __nv_bfloat16 g_Wqkvhi[384 * CC];            // Wq(64) ; Wk(64) ; Wv(256) rows
__device__ __nv_bfloat16 g_Wqkvlo[384 * CC];
__device__ __nv_bfloat16 g_Wthi[CC * CC];
__device__ __nv_bfloat16 g_Wtlo[CC * CC];
__device__ float g_T[(size_t)BB * CC * NN];
__device__ float g_invrs[BB * NN];                      // 1 / softmax row sums
__device__ float g_colsum[BB * NN];
__device__ float g_sum[CC];
__device__ float g_sumsq[CC];
__device__ float g_scale[CC];
__device__ float g_shift[CC];

// ---------------- PTX helpers ----------------
__device__ __forceinline__ void mma16816(float* c, const uint32_t* a, const uint32_t* b) {
    asm volatile(
        "mma.sync.aligned.m16n8k16.row.col.f32.bf16.bf16.f32 "
        "{%0,%1,%2,%3}, {%4,%5,%6,%7}, {%8,%9}, {%0,%1,%2,%3};\n"
        : "+f"(c[0]), "+f"(c[1]), "+f"(c[2]), "+f"(c[3])
        : "r"(a[0]), "r"(a[1]), "r"(a[2]), "r"(a[3]), "r"(b[0]), "r"(b[1]));
}
__device__ __forceinline__ void ldsm4(uint32_t* r, uint32_t addr) {
    asm volatile("ldmatrix.sync.aligned.m8n8.x4.shared.b16 {%0,%1,%2,%3}, [%4];"
        : "=r"(r[0]), "=r"(r[1]), "=r"(r[2]), "=r"(r[3]) : "r"(addr));
}
__device__ __forceinline__ void ldsm4t(uint32_t* r, uint32_t addr) {
    asm volatile("ldmatrix.sync.aligned.m8n8.x4.trans.shared.b16 {%0,%1,%2,%3}, [%4];"
        : "=r"(r[0]), "=r"(r[1]), "=r"(r[2]), "=r"(r[3]) : "r"(addr));
}
__device__ __forceinline__ void cpasync16(uint32_t saddr, const void* g) {
    asm volatile("cp.async.cg.shared.global [%0], [%1], 16;" :: "r"(saddr), "l"(g));
}
__device__ __forceinline__ void cp_commit() { asm volatile("cp.async.commit_group;" ::: "memory"); }

__device__ __forceinline__ void split1(float v, __nv_bfloat16& h, __nv_bfloat16& l) {
    h = __float2bfloat16(v);
    l = __float2bfloat16(v - __bfloat162float(h));
}
__device__ __forceinline__ void split_pack(float a, float b, __nv_bfloat162& hi2, __nv_bfloat162& lo2) {
    __nv_bfloat16 ha, la, hb, lb;
    split1(a, ha, la); split1(b, hb, lb);
    hi2.x = ha; hi2.y = hb;
    lo2.x = la; lo2.y = lb;
}

// ---------------- unified bf16-split tensor-core GEMM ----------------
// C[M,N] = (Ahi+Alo)[M,K] @ (B0(+B1))[K,N]     ldb = ldc = NN
// EPI: 1 = QKV projection epilogue  2 = transform (+bias, BN stats)  3 = xr->d split
#define SA_STRIDE 24   // halves per A row
#define SB_STRIDE 136  // halves per B row

template<int NB, int EPI>
__global__ __launch_bounds__(256)
void mma_gemm_kernel(const __nv_bfloat16* __restrict__ Ahi, const __nv_bfloat16* __restrict__ Alo,
                     int lda, size_t aBS,
                     const __nv_bfloat16* __restrict__ B0, const __nv_bfloat16* __restrict__ B1,
                     size_t bBS,
                     float* __restrict__ C, size_t cBS, int K,
                     const float* __restrict__ bias,
                     const float* __restrict__ aux, size_t auxBS)
{
    __shared__ __align__(16) __nv_bfloat16 sA[2][2][128 * SA_STRIDE];
    __shared__ __align__(16) __nv_bfloat16 sB[2][NB][16 * SB_STRIDE];

    const int bz = blockIdx.z;
    Ahi += (size_t)bz * aBS;  Alo += (size_t)bz * aBS;
    B0  += (size_t)bz * bBS;
    if (NB == 2) B1 += (size_t)bz * bBS;
    C += (size_t)bz * cBS;
    if (EPI == 3) aux += (size_t)bz * auxBS;

    const int row0 = blockIdx.y * 128;
    const int col0 = blockIdx.x * 128;
    const int tid  = threadIdx.x;
    const int lane = tid & 31, warp = tid >> 5;
    const int wm = warp & 3;
    const int wn = warp >> 2;

    const int ar = tid >> 1, ac = (tid & 1) * 8;
    const int bk = tid >> 4, bc = (tid & 15) * 8;
    const size_t gA = (size_t)(row0 + ar) * lda + ac;
    const size_t gB = (size_t)bk * NN + col0 + bc;

    const uint32_t sAbase = (uint32_t)__cvta_generic_to_shared(&sA[0][0][0]);
    const uint32_t sBbase = (uint32_t)__cvta_generic_to_shared(&sB[0][0][0]);
    const uint32_t sAst = (uint32_t)(ar * SA_STRIDE + ac) * 2;
    const uint32_t sBst = (uint32_t)(bk * SB_STRIDE + bc) * 2;

    constexpr uint32_t A_PLANE = 128 * SA_STRIDE * 2;
    constexpr uint32_t B_PLANE = 16 * SB_STRIDE * 2;
    constexpr uint32_t A_STAGE = 2 * A_PLANE;
    constexpr uint32_t B_STAGE = NB * B_PLANE;

    float acc[2][8][4];
#pragma unroll
    for (int i = 0; i < 2; i++)
#pragma unroll
        for (int j = 0; j < 8; j++)
#pragma unroll
            for (int k = 0; k < 4; k++) acc[i][j][k] = 0.f;

    const int KT = K >> 4;

    auto issue = [&](int kt, int stage) {
        const size_t ka = gA + (size_t)kt * 16;
        const size_t kb = gB + (size_t)kt * 16 * NN;
        const uint32_t aoff = sAbase + stage * A_STAGE + sAst;
        const uint32_t boff = sBbase + stage * B_STAGE + sBst;
        cpasync16(aoff,           Ahi + ka);
        cpasync16(aoff + A_PLANE, Alo + ka);
        cpasync16(boff,           B0 + kb);
        if (NB == 2) cpasync16(boff + B_PLANE, B1 + kb);
    };

    issue(0, 0); cp_commit();

    const int lr = lane & 15, lc8 = (lane >> 4) * 8;
    const uint32_t aAddrBase = sAbase + ((wm * 32 + lr) * SA_STRIDE + lc8) * 2;
    const uint32_t bAddrBase = sBbase + (lr * SB_STRIDE + wn * 64 + lc8) * 2;

    for (int kt = 0; kt < KT; kt++) {
        const int cur = kt & 1;
        if (kt + 1 < KT) {
            issue(kt + 1, cur ^ 1); cp_commit();
            asm volatile("cp.async.wait_group 1;" ::: "memory");
        } else {
            asm volatile("cp.async.wait_group 0;" ::: "memory");
        }
        __syncthreads();

        const uint32_t aS = cur * A_STAGE;
        const uint32_t bS = cur * B_STAGE;

        uint32_t ah[2][4], al[2][4];
#pragma unroll
        for (int mi = 0; mi < 2; mi++) {
            ldsm4(ah[mi], aAddrBase + aS + mi * 16 * SA_STRIDE * 2);
            ldsm4(al[mi], aAddrBase + aS + A_PLANE + mi * 16 * SA_STRIDE * 2);
        }
        uint32_t bh[4][4], bl[4][4];
#pragma unroll
        for (int j = 0; j < 4; j++) {
            ldsm4t(bh[j], bAddrBase + bS + j * 16 * 2);
            if (NB == 2) ldsm4t(bl[j], bAddrBase + bS + B_PLANE + j * 16 * 2);
        }
#pragma unroll
        for (int mi = 0; mi < 2; mi++) {
#pragma unroll
            for (int j = 0; j < 4; j++) {
                mma16816(acc[mi][2 * j],     ah[mi], &bh[j][0]);
                mma16816(acc[mi][2 * j + 1], ah[mi], &bh[j][2]);
                if (NB == 2) {
                    mma16816(acc[mi][2 * j],     ah[mi], &bl[j][0]);
                    mma16816(acc[mi][2 * j + 1], ah[mi], &bl[j][2]);
                }
                mma16816(acc[mi][2 * j],     al[mi], &bh[j][0]);
                mma16816(acc[mi][2 * j + 1], al[mi], &bh[j][2]);
            }
        }
        __syncthreads();
    }

    const int gid = lane >> 2, t4 = lane & 3;

    if (EPI == 1) {
        const int by = blockIdx.y;
#pragma unroll
        for (int mi = 0; mi < 2; mi++)
#pragma unroll
            for (int nj = 0; nj < 8; nj++) {
                const int r = row0 + wm * 32 + mi * 16 + gid;
                const int col = col0 + wn * 64 + nj * 8 + t4 * 2;
                const float v00 = acc[mi][nj][0], v01 = acc[mi][nj][1];
                const float v10 = acc[mi][nj][2], v11 = acc[mi][nj][3];
                if (by == 0) {
                    if (r < 64) {  // Q -> transposed split [n][o]
                        const size_t base = (size_t)bz * NN * CQ;
                        __nv_bfloat16 h, l;
                        split1(v00, h, l); g_Qthi[base + (size_t)col * CQ + r] = h;       g_Qtlo[base + (size_t)col * CQ + r] = l;
                        split1(v01, h, l); g_Qthi[base + (size_t)(col + 1) * CQ + r] = h; g_Qtlo[base + (size_t)(col + 1) * CQ + r] = l;
                        split1(v10, h, l); g_Qthi[base + (size_t)col * CQ + r + 8] = h;       g_Qtlo[base + (size_t)col * CQ + r + 8] = l;
                        split1(v11, h, l); g_Qthi[base + (size_t)(col + 1) * CQ + r + 8] = h; g_Qtlo[base + (size_t)(col + 1) * CQ + r + 8] = l;
                    } else {       // K -> split [o][n]
                        const int kr = r - 64;
                        const size_t base = (size_t)bz * CQ * NN;
                        __nv_bfloat162 h2, l2;
                        split_pack(v00, v01, h2, l2);
                        *(__nv_bfloat162*)&g_Khi[base + (size_t)kr * NN + col] = h2;
                        *(__nv_bfloat162*)&g_Klo[base + (size_t)kr * NN + col] = l2;
                        split_pack(v10, v11, h2, l2);
                        *(__nv_bfloat162*)&g_Khi[base + (size_t)(kr + 8) * NN + col] = h2;
                        *(__nv_bfloat162*)&g_Klo[base + (size_t)(kr + 8) * NN + col] = l2;
                    }
                } else {           // V rows (+bias)
                    const int vr = r - 128;
                    const size_t base = (size_t)bz * CC * NN;
                    const float b0 = bias[vr], b1 = bias[vr + 8];
                    __nv_bfloat162 h2, l2;
                    split_pack(v00 + b0, v01 + b0, h2, l2);
                    *(__nv_bfloat162*)&g_Vhi[base + (size_t)vr * NN + col] = h2;
                    *(__nv_bfloat162*)&g_Vlo[base + (size_t)vr * NN + col] = l2;
                    split_pack(v10 + b1, v11 + b1, h2, l2);
                    *(__nv_bfloat162*)&g_Vhi[base + (size_t)(vr + 8) * NN + col] = h2;
                    *(__nv_bfloat162*)&g_Vlo[base + (size_t)(vr + 8) * NN + col] = l2;
                }
            }
    }

    if (EPI == 2) {
        float ssum[2][2] = {{0.f, 0.f}, {0.f, 0.f}};
        float ssq[2][2]  = {{0.f, 0.f}, {0.f, 0.f}};
#pragma unroll
        for (int mi = 0; mi < 2; mi++)
#pragma unroll
            for (int nj = 0; nj < 8; nj++) {
                const int r = row0 + wm * 32 + mi * 16 + gid;
                const int col = col0 + wn * 64 + nj * 8 + t4 * 2;
                const float b0 = bias[r], b1 = bias[r + 8];
                const float v00 = acc[mi][nj][0] + b0, v01 = acc[mi][nj][1] + b0;
                const float v10 = acc[mi][nj][2] + b1, v11 = acc[mi][nj][3] + b1;
                *(float2*)&C[(size_t)r * NN + col]       = make_float2(v00, v01);
                *(float2*)&C[(size_t)(r + 8) * NN + col] = make_float2(v10, v11);
                ssum[mi][0] += v00 + v01;  ssq[mi][0] += v00 * v00 + v01 * v01;
                ssum[mi][1] += v10 + v11;  ssq[mi][1] += v10 * v10 + v11 * v11;
            }
#pragma unroll
        for (int mi = 0; mi < 2; mi++)
#pragma unroll
            for (int h = 0; h < 2; h++) {
                const int r = row0 + wm * 32 + mi * 16 + gid + h * 8;
                atomicAdd(&g_sum[r], ssum[mi][h]);
                atomicAdd(&g_sumsq[r], ssq[mi][h]);
            }
    }

    if (EPI == 3) {
#pragma unroll
        for (int mi = 0; mi < 2; mi++)
#pragma unroll
            for (int nj = 0; nj < 8; nj++) {
                const int r = row0 + wm * 32 + mi * 16 + gid;
                const int col = col0 + wn * 64 + nj * 8 + t4 * 2;
                const float cs0 = 1.0f / (1e-9f + g_colsum[bz * NN + col]);
                const float cs1 = 1.0f / (1e-9f + g_colsum[bz * NN + col + 1]);
                const size_t base = (size_t)bz * CC * NN;
                const float d00 = aux[(size_t)r * NN + col]       - acc[mi][nj][0] * cs0;
                const float d01 = aux[(size_t)r * NN + col + 1]   - acc[mi][nj][1] * cs1;
                const float d10 = aux[(size_t)(r + 8) * NN + col]     - acc[mi][nj][2] * cs0;
                const float d11 = aux[(size_t)(r + 8) * NN + col + 1] - acc[mi][nj][3] * cs1;
                __nv_bfloat162 h2, l2;
                split_pack(d00, d01, h2, l2);
                *(__nv_bfloat162*)&g_dhi[base + (size_t)r * NN + col] = h2;
                *(__nv_bfloat162*)&g_dlo[base + (size_t)r * NN + col] = l2;
                split_pack(d10, d11, h2, l2);
                *(__nv_bfloat162*)&g_dhi[base + (size_t)(r + 8) * NN + col] = h2;
                *(__nv_bfloat162*)&g_dlo[base + (size_t)(r + 8) * NN + col] = l2;
            }
    }
}

// ---------------- fused energy + exp + rowsum -> U bf16 ----------------
// One CTA per 128-row stripe; loops over 32 column tiles of 128.
// E = Qt @ K (3-product bf16 split), U = exp(E) (no max needed: |E| < ~55),
// writes U bf16, stores invrs = 1/rowsum.
#define QA_ST 72   // halves per Q row (64 + 8 pad)
#define KB_ST 136  // halves per K-tile row (128 + 8 pad)

__global__ __launch_bounds__(256)
void attn_kernel()
{
    extern __shared__ __align__(16) char dsm[];
    __nv_bfloat16* sQ = (__nv_bfloat16*)dsm;                 // [2][128*QA_ST]
    __nv_bfloat16* sK = sQ + 2 * 128 * QA_ST;                // [2][2][64*KB_ST]
    float* s_rs = (float*)(sK + 2 * 2 * 64 * KB_ST);         // [128]

    const int b  = blockIdx.y;
    const int r0 = blockIdx.x * 128;
    const int tid = threadIdx.x;
    const int lane = tid & 31, warp = tid >> 5;
    const int wm = warp & 3, wn = warp >> 2;

    if (tid < 128) s_rs[tid] = 0.f;

    const uint32_t sQb = (uint32_t)__cvta_generic_to_shared(sQ);
    const uint32_t sKb = (uint32_t)__cvta_generic_to_shared(sK);

    // Q loads (one commit group)
    const __nv_bfloat16* Qhi = g_Qthi + (size_t)b * NN * CQ;
    const __nv_bfloat16* Qlo = g_Qtlo + (size_t)b * NN * CQ;
#pragma unroll
    for (int p = 0; p < 4; p++) {
        const int idx = p * 256 + tid;
        const int row = idx >> 3, c8 = (idx & 7) * 8;
        cpasync16(sQb + (uint32_t)(row * QA_ST + c8) * 2,
                  Qhi + (size_t)(r0 + row) * CQ + c8);
        cpasync16(sQb + (uint32_t)(128 * QA_ST + row * QA_ST + c8) * 2,
                  Qlo + (size_t)(r0 + row) * CQ + c8);
    }
    cp_commit();

    const __nv_bfloat16* Khi = g_Khi + (size_t)b * CQ * NN;
    const __nv_bfloat16* Klo = g_Klo + (size_t)b * CQ * NN;
    const int kr = tid >> 4, kc8 = (tid & 15) * 8;

    auto issueK = [&](int tile, int stage) {
        const int c0 = tile * 128;
        const uint32_t base = sKb + (uint32_t)stage * (2 * 64 * KB_ST * 2);
#pragma unroll
        for (int c = 0; c < 4; c++) {
            const int r = kr + c * 16;
            cpasync16(base + (uint32_t)(r * KB_ST + kc8) * 2,
                      Khi + (size_t)r * NN + c0 + kc8);
            cpasync16(base + (uint32_t)(64 * KB_ST + r * KB_ST + kc8) * 2,
                      Klo + (size_t)r * NN + c0 + kc8);
        }
        cp_commit();
    };

    issueK(0, 0);

    const int lr = lane & 15, lc8 = (lane >> 4) * 8;
    const uint32_t aBase = sQb + (uint32_t)((wm * 32 + lr) * QA_ST + lc8) * 2;
    const uint32_t bBase = sKb + (uint32_t)(lr * KB_ST + wn * 64 + lc8) * 2;
    constexpr uint32_t QPLANE = 128 * QA_ST * 2;
    constexpr uint32_t KPLANE = 64 * KB_ST * 2;
    constexpr uint32_t KSTAGE = 2 * KPLANE;

    const int gid = lane >> 2, t4 = lane & 3;
    float rowsum[2][2] = {{0.f, 0.f}, {0.f, 0.f}};
    __nv_bfloat16* U = g_A + (size_t)b * NN * NN;

    for (int tile = 0; tile < 32; tile++) {
        const int cur = tile & 1;
        if (tile + 1 < 32) {
            issueK(tile + 1, cur ^ 1);
            asm volatile("cp.async.wait_group 1;" ::: "memory");
        } else {
            asm volatile("cp.async.wait_group 0;" ::: "memory");
        }
        __syncthreads();

        const uint32_t bS = cur * KSTAGE;

        float acc[2][8][4];
#pragma unroll
        for (int i = 0; i < 2; i++)
#pragma unroll
            for (int j = 0; j < 8; j++)
#pragma unroll
                for (int k = 0; k < 4; k++) acc[i][j][k] = 0.f;

#pragma unroll
        for (int ch = 0; ch < 4; ch++) {
            uint32_t ah[2][4], al[2][4];
#pragma unroll
            for (int mi = 0; mi < 2; mi++) {
                ldsm4(ah[mi], aBase + ch * 32 + mi * 16 * QA_ST * 2);
                ldsm4(al[mi], aBase + QPLANE + ch * 32 + mi * 16 * QA_ST * 2);
            }
            uint32_t bh[4][4], bl[4][4];
#pragma unroll
            for (int j = 0; j < 4; j++) {
                ldsm4t(bh[j], bBase + bS + ch * 16 * KB_ST * 2 + j * 16 * 2);
                ldsm4t(bl[j], bBase + bS + KPLANE + ch * 16 * KB_ST * 2 + j * 16 * 2);
            }
#pragma unroll
            for (int mi = 0; mi < 2; mi++)
#pragma unroll
                for (int j = 0; j < 4; j++) {
                    mma16816(acc[mi][2 * j],     ah[mi], &bh[j][0]);
                    mma16816(acc[mi][2 * j + 1], ah[mi], &bh[j][2]);
                    mma16816(acc[mi][2 * j],     ah[mi], &bl[j][0]);
                    mma16816(acc[mi][2 * j + 1], ah[mi], &bl[j][2]);
                    mma16816(acc[mi][2 * j],     al[mi], &bh[j][0]);
                    mma16816(acc[mi][2 * j + 1], al[mi], &bh[j][2]);
                }
        }

        // exp + rowsum + bf16 store
        const int c0 = tile * 128;
#pragma unroll
        for (int mi = 0; mi < 2; mi++)
#pragma unroll
            for (int nj = 0; nj < 8; nj++) {
                const int row = r0 + wm * 32 + mi * 16 + gid;
                const int col = c0 + wn * 64 + nj * 8 + t4 * 2;
                const float e00 = __expf(acc[mi][nj][0]);
                const float e01 = __expf(acc[mi][nj][1]);
                const float e10 = __expf(acc[mi][nj][2]);
                const float e11 = __expf(acc[mi][nj][3]);
                rowsum[mi][0] += e00 + e01;
                rowsum[mi][1] += e10 + e11;
                __nv_bfloat162 p0, p1;
                p0.x = __float2bfloat16(e00); p0.y = __float2bfloat16(e01);
                p1.x = __float2bfloat16(e10); p1.y = __float2bfloat16(e11);
                *(__nv_bfloat162*)&U[(size_t)row * NN + col] = p0;
                *(__nv_bfloat162*)&U[(size_t)(row + 8) * NN + col] = p1;
            }
        __syncthreads();
    }

    // reduce row sums: over quad lanes, then across warps via shared atomics
#pragma unroll
    for (int mi = 0; mi < 2; mi++)
#pragma unroll
        for (int h = 0; h < 2; h++) {
            float v = rowsum[mi][h];
            v += __shfl_xor_sync(0xffffffffu, v, 1);
            v += __shfl_xor_sync(0xffffffffu, v, 2);
            if (t4 == 0) atomicAdd(&s_rs[wm * 32 + mi * 16 + gid + h * 8], v);
        }
    __syncthreads();
    if (tid < 128) g_invrs[b * NN + r0 + tid] = 1.0f / s_rs[tid];
}

// ---------------- V in-place rescale: V' = V * invrs[n] ----------------
__global__ void vrescale_kernel()
{
    const int b = blockIdx.z;
    const int idx = blockIdx.x * 256 + threadIdx.x;       // over CC*NN/2 pairs
    const int m2 = idx & (NN / 2 - 1);
    const size_t o = (size_t)b * CC * (NN / 2) + idx;
    __nv_bfloat162* H = (__nv_bfloat162*)g_Vhi;
    __nv_bfloat162* L = (__nv_bfloat162*)g_Vlo;
    const __nv_bfloat162 h2 = H[o], l2 = L[o];
    const float w0 = g_invrs[b * NN + 2 * m2];
    const float w1 = g_invrs[b * NN + 2 * m2 + 1];
    const float v0 = (__bfloat162float(h2.x) + __bfloat162float(l2.x)) * w0;
    const float v1 = (__bfloat162float(h2.y) + __bfloat162float(l2.y)) * w1;
    __nv_bfloat162 nh, nl;
    split_pack(v0, v1, nh, nl);
    H[o] = nh; L[o] = nl;
}

// ---------------- weighted column sums: colsum[m] = sum_n U[n,m]*invrs[n] ----------------
__global__ void colsum_kernel()
{
    const int m2 = blockIdx.x * 256 + threadIdx.x;
    const int b = blockIdx.z;
    const int n0 = blockIdx.y * 128;
    const __nv_bfloat162* A2 = (const __nv_bfloat162*)(g_A + (size_t)b * NN * NN);
    float s0 = 0.f, s1 = 0.f;
#pragma unroll 4
    for (int n = 0; n < 128; n++) {
        const float w = g_invrs[b * NN + n0 + n];
        const __nv_bfloat162 a = A2[(size_t)(n0 + n) * (NN / 2) + m2];
        s0 += __bfloat162float(a.x) * w;
        s1 += __bfloat162float(a.y) * w;
    }
    atomicAdd(&g_colsum[b * NN + 2 * m2 + 0], s0);
    atomicAdd(&g_colsum[b * NN + 2 * m2 + 1], s1);
}

// ---------------- splits ----------------
__global__ void split4_kernel(const float* __restrict__ src, size_t srcBS,
                              __nv_bfloat16* __restrict__ hi, __nv_bfloat16* __restrict__ lo,
                              size_t dstBS)
{
    const size_t i4 = (size_t)blockIdx.x * 256 + threadIdx.x;
    const float4 v = ((const float4*)(src + (size_t)blockIdx.z * srcBS))[i4];
    __nv_bfloat162 ha, la, hb, lb;
    split_pack(v.x, v.y, ha, la);
    split_pack(v.z, v.w, hb, lb);
    uint2 hv, lv;
    hv.x = *(uint32_t*)&ha; hv.y = *(uint32_t*)&hb;
    lv.x = *(uint32_t*)&la; lv.y = *(uint32_t*)&lb;
    ((uint2*)(hi + (size_t)blockIdx.z * dstBS))[i4] = hv;
    ((uint2*)(lo + (size_t)blockIdx.z * dstBS))[i4] = lv;
}

__global__ void wqkv_split_kernel(const float* __restrict__ Wq, const float* __restrict__ Wk,
                                  const float* __restrict__ Wv)
{
    const int t = blockIdx.x * 256 + threadIdx.x;
    float v;
    if (t < 64 * CC) v = Wq[t];
    else if (t < 128 * CC) v = Wk[t - 64 * CC];
    else v = Wv[t - 128 * CC];
    __nv_bfloat16 h, l;
    split1(v, h, l);
    g_Wqkvhi[t] = h; g_Wqkvlo[t] = l;
}

// ---------------- misc ----------------
__global__ void zero_kernel()
{
    const int t = blockIdx.x * 256 + threadIdx.x;
    if (t < CC) { g_sum[t] = 0.f; g_sumsq[t] = 0.f; }
    if (t < BB * NN) g_colsum[t] = 0.f;
}

__global__ void bn_finalize_kernel(const float* __restrict__ gamma, const float* __restrict__ beta)
{
    const int c = threadIdx.x;
    const float cnt = (float)(BB * NN);
    const float mean = g_sum[c] / cnt;
    const float var = g_sumsq[c] / cnt - mean * mean;
    const float sc = gamma[c] * rsqrtf(var + 1e-5f);
    g_scale[c] = sc;
    g_shift[c] = beta[c] - mean * sc;
}

__global__ void final_kernel(const float* __restrict__ x, float* __restrict__ out)
{
    const size_t idx = (size_t)blockIdx.x * 256 + threadIdx.x;
    const int c = (int)((idx >> 12) & (CC - 1));
    const float t = g_T[idx] * g_scale[c] + g_shift[c];
    out[idx] = x[idx] + fmaxf(t, 0.f);
}

// ---------------- launch ----------------
extern "C" void kernel_launch(void* const* d_in, const int* in_sizes, int n_in,
                              void* d_out, int out_size)
{
    const float* x     = (const float*)d_in[0];
    const float* Wq    = (const float*)d_in[1];
    const float* Wk    = (const float*)d_in[2];
    const float* Wv    = (const float*)d_in[3];
    const float* bv    = (const float*)d_in[4];
    const float* Wt    = (const float*)d_in[5];
    const float* bt    = (const float*)d_in[6];
    const float* gamma = (const float*)d_in[7];
    const float* beta  = (const float*)d_in[8];
    float* out = (float*)d_out;

    float *pT;
    __nv_bfloat16 *pA, *pXhi, *pXlo, *pVhi, *pVlo, *pDhi, *pDlo;
    __nv_bfloat16 *pQthi, *pQtlo, *pKhi, *pKlo, *pWqkvhi, *pWqkvlo, *pWthi, *pWtlo;
    cudaGetSymbolAddress((void**)&pT, g_T);
    cudaGetSymbolAddress((void**)&pA, g_A);
    cudaGetSymbolAddress((void**)&pXhi, g_xhi);
    cudaGetSymbolAddress((void**)&pXlo, g_xlo);
    cudaGetSymbolAddress((void**)&pVhi, g_Vhi);
    cudaGetSymbolAddress((void**)&pVlo, g_Vlo);
    cudaGetSymbolAddress((void**)&pDhi, g_dhi);
    cudaGetSymbolAddress((void**)&pDlo, g_dlo);
    cudaGetSymbolAddress((void**)&pQthi, g_Qthi);
    cudaGetSymbolAddress((void**)&pQtlo, g_Qtlo);
    cudaGetSymbolAddress((void**)&pKhi, g_Khi);
    cudaGetSymbolAddress((void**)&pKlo, g_Klo);
    cudaGetSymbolAddress((void**)&pWqkvhi, g_Wqkvhi);
    cudaGetSymbolAddress((void**)&pWqkvlo, g_Wqkvlo);
    cudaGetSymbolAddress((void**)&pWthi, g_Wthi);
    cudaGetSymbolAddress((void**)&pWtlo, g_Wtlo);

    // fused attention kernel needs 107 KB dynamic smem
    const int attn_smem = (2 * 128 * QA_ST + 2 * 2 * 64 * KB_ST) * 2 + 128 * 4;
    cudaFuncSetAttribute(attn_kernel, cudaFuncAttributeMaxDynamicSharedMemorySize, attn_smem);

    zero_kernel<<<BB * NN / 256, 256>>>();
    wqkv_split_kernel<<<384 * CC / 256, 256>>>(Wq, Wk, Wv);
    split4_kernel<<<dim3(CC * CC / 1024, 1, 1), 256>>>(Wt, 0, pWthi, pWtlo, 0);
    split4_kernel<<<dim3(CC * NN / 1024, 1, BB), 256>>>(x, (size_t)CC * NN, pXhi, pXlo, (size_t)CC * NN);

    // stacked QKV projection: [384,256] @ [256,4096]; epilogue writes Qt/K/V splits
    mma_gemm_kernel<2, 1><<<dim3(NN / 128, 3, BB), 256>>>(
        pWqkvhi, pWqkvlo, CC, 0,
        pXhi, pXlo, (size_t)CC * NN,
        pT /*unused*/, 0, CC, bv, nullptr, 0);

    // fused energy + exp + rowsum -> U (bf16), invrs
    attn_kernel<<<dim3(NN / 128, BB), 256, attn_smem>>>();

    // V' = V * invrs[n] (in place)
    vrescale_kernel<<<dim3(CC * NN / 512, 1, BB), 256>>>();

    // weighted column sums for L1 renorm
    colsum_kernel<<<dim3(NN / 512, NN / 128, BB), 256>>>();

    // x_r = V' @ U; epilogue computes d = x - xr*colscale, writes d splits
    mma_gemm_kernel<1, 3><<<dim3(NN / 128, CC / 128, BB), 256>>>(
        pVhi, pVlo, NN, (size_t)CC * NN,
        pA, nullptr, (size_t)NN * NN,
        pT /*unused*/, 0, NN, nullptr, x, (size_t)CC * NN);

    // t = Wt @ d + bt, with BN stats -> g_T
    mma_gemm_kernel<2, 2><<<dim3(NN / 128, CC / 128, BB), 256>>>(
        pWthi, pWtlo, CC, 0,
        pDhi, pDlo, (size_t)CC * NN,
        pT, (size_t)CC * NN, CC, bt, nullptr, 0);

    bn_finalize_kernel<<<1, CC>>>(gamma, beta);

    final_kernel<<<(size_t)BB * CC * NN / 256, 256>>>(x, out);
}